// round 6
// baseline (speedup 1.0000x reference)
#include <cuda_runtime.h>

#define IN_DIM   256
#define OUT_DIM  256
#define N_KNOTS  9
#define NB       5
#define ROWS     8            // batch rows per main-kernel block
#define THREADS  256
#define CW       (OUT_DIM * NB)      // 1280 coeff words per i-row
#define BW       (ROWS * NB)         // 40 basis words per (tile, i)

// basis scratch: [tile][i][n][r8], tile = b/8  (4096/8 * 256 * 40 floats = 21 MB)
__device__ float g_basis[(4096 / ROWS) * IN_DIM * BW];

// ---------------------------------------------------------------------------
// Kernel A: B-spline basis -> g_basis   (tile = blockIdx, i = threadIdx)
// ---------------------------------------------------------------------------
__global__ __launch_bounds__(THREADS)
void kan_basis(const float* __restrict__ x,
               const float* __restrict__ grids)
{
    __shared__ float sm[IN_DIM * 41];            // padded stride 41: conflict-free STS
    const int t    = threadIdx.x;
    const int tile = blockIdx.x;
    const int b0   = tile * ROWS;
    const int i    = t;

    float tk[N_KNOTS];
    #pragma unroll
    for (int k = 0; k < N_KNOTS; k++) tk[k] = grids[i * N_KNOTS + k];

    float iL1[7], iR1[7], iL2[6], iR2[6], iL3[5], iR3[5];
    #pragma unroll
    for (int j = 0; j < 7; j++) { iL1[j] = 1.f / (tk[j+1] - tk[j]); iR1[j] = 1.f / (tk[j+2] - tk[j+1]); }
    #pragma unroll
    for (int j = 0; j < 6; j++) { iL2[j] = 1.f / (tk[j+2] - tk[j]); iR2[j] = 1.f / (tk[j+3] - tk[j+1]); }
    #pragma unroll
    for (int j = 0; j < 5; j++) { iL3[j] = 1.f / (tk[j+3] - tk[j]); iR3[j] = 1.f / (tk[j+4] - tk[j+1]); }

    #pragma unroll
    for (int r = 0; r < ROWS; r++) {
        const float xv = x[(size_t)(b0 + r) * IN_DIM + i];
        float bas[8];
        #pragma unroll
        for (int j = 0; j < 8; j++)
            bas[j] = (xv >= tk[j] && xv < tk[j+1]) ? 1.0f : 0.0f;
        #pragma unroll
        for (int j = 0; j < 7; j++)
            bas[j] = (xv - tk[j]) * iL1[j] * bas[j] + (tk[j+2] - xv) * iR1[j] * bas[j+1];
        #pragma unroll
        for (int j = 0; j < 6; j++)
            bas[j] = (xv - tk[j]) * iL2[j] * bas[j] + (tk[j+3] - xv) * iR2[j] * bas[j+1];
        #pragma unroll
        for (int j = 0; j < 5; j++)
            bas[j] = (xv - tk[j]) * iL3[j] * bas[j] + (tk[j+4] - xv) * iR3[j] * bas[j+1];

        #pragma unroll
        for (int n = 0; n < NB; n++)
            sm[i * 41 + n * 8 + r] = bas[n];      // layout [i][n][r8] (padded)
    }
    __syncthreads();

    // coalesced write-out: [tile][i][n][r8], 10 float4 per thread
    const size_t base = (size_t)tile * (IN_DIM * BW);
    #pragma unroll
    for (int k = 0; k < 10; k++) {
        const int w0 = 4 * (t + THREADS * k);     // flat word in [i][40]
        float4 v;
        v.x = sm[((w0 + 0) / 40) * 41 + (w0 + 0) % 40];
        v.y = sm[((w0 + 1) / 40) * 41 + (w0 + 1) % 40];
        v.z = sm[((w0 + 2) / 40) * 41 + (w0 + 2) % 40];
        v.w = sm[((w0 + 3) / 40) * 41 + (w0 + 3) % 40];
        *reinterpret_cast<float4*>(&g_basis[base + w0]) = v;
    }
}

// ---------------------------------------------------------------------------
// Kernel B: acts + y.   smem = coeff double-buffer (linear [o][n]) + basis stage
// ---------------------------------------------------------------------------
#define SC_BUF   (2 * CW)                 // 2 i-rows per buffer = 2560 words
#define SB_BUF   (2 * BW)                 // 2 i-rows of basis   = 80 words
#define SMEM_WORDS (2 * SC_BUF + 2 * SB_BUF)
#define SMEM_BYTES (SMEM_WORDS * 4)       // 21.1 KB -> smem no longer caps occ

__global__ __launch_bounds__(THREADS, 3)
void kan_main(const float* __restrict__ coef,
              float* __restrict__ y,
              float* __restrict__ acts)
{
    extern __shared__ float smem[];
    float* scoef = smem;                   // [buf2][row2][1280]  (native [o][n])
    float* sbas  = smem + 2 * SC_BUF;      // [buf2][row2][n5][r8]

    const int t    = threadIdx.x;
    const int tile = blockIdx.x;
    const int b0   = tile * ROWS;
    const int o4   = (t & 63) * 4;
    const int rg2  = (t >> 6) * 2;

    const size_t gb_base = (size_t)tile * (IN_DIM * BW);

    // prologue: stage i = 0,1 into buffer 0
    {
        float p[10];
        #pragma unroll
        for (int k = 0; k < 10; k++) p[k] = coef[t + THREADS * k];
        #pragma unroll
        for (int k = 0; k < 10; k++) scoef[t + THREADS * k] = p[k];
        if (t < SB_BUF) sbas[t] = g_basis[gb_base + t];
    }
    __syncthreads();

    float4 acc[2];
    acc[0] = make_float4(0.f, 0.f, 0.f, 0.f);
    acc[1] = make_float4(0.f, 0.f, 0.f, 0.f);

    float* actp = acts + (size_t)(b0 + rg2) * (IN_DIM * OUT_DIM) + o4;

    for (int ip = 0; ip < IN_DIM / 2; ip++) {
        const int buf   = ip & 1;
        const int inext = 2 * ip + 2;
        const bool has  = inext < IN_DIM;

        // prefetch next 2 coeff rows (coalesced) + next 2 basis chunks
        float p[10], pb;
        if (has) {
            const float* src = coef + (size_t)inext * CW;
            #pragma unroll
            for (int k = 0; k < 10; k++) p[k] = src[t + THREADS * k];
            if (t < SB_BUF) pb = g_basis[gb_base + (size_t)inext * BW + t];
        }

        #pragma unroll
        for (int s = 0; s < 2; s++) {
            const int i = 2 * ip + s;

            // coeff: 20 consecutive words at o4*5 -> 5 conflict-free LDS.128
            float4 q[5];
            const float4* cb = reinterpret_cast<const float4*>(
                &scoef[buf * SC_BUF + s * CW + o4 * NB]);
            #pragma unroll
            for (int j = 0; j < 5; j++) q[j] = cb[j];
            const float* f = reinterpret_cast<const float*>(q);  // f[o*5+n]

            // basis: 5 broadcast LDS.64, bsv[n] = rows (rg2, rg2+1)
            float2 bsv[NB];
            #pragma unroll
            for (int n = 0; n < NB; n++)
                bsv[n] = *reinterpret_cast<const float2*>(
                    &sbas[buf * SB_BUF + s * BW + n * 8 + rg2]);

            #pragma unroll
            for (int r = 0; r < 2; r++) {
                const float bb0 = r ? bsv[0].y : bsv[0].x;
                const float bb1 = r ? bsv[1].y : bsv[1].x;
                const float bb2 = r ? bsv[2].y : bsv[2].x;
                const float bb3 = r ? bsv[3].y : bsv[3].x;
                const float bb4 = r ? bsv[4].y : bsv[4].x;
                float4 v;
                v.x = bb0*f[ 0] + bb1*f[ 1] + bb2*f[ 2] + bb3*f[ 3] + bb4*f[ 4];
                v.y = bb0*f[ 5] + bb1*f[ 6] + bb2*f[ 7] + bb3*f[ 8] + bb4*f[ 9];
                v.z = bb0*f[10] + bb1*f[11] + bb2*f[12] + bb3*f[13] + bb4*f[14];
                v.w = bb0*f[15] + bb1*f[16] + bb2*f[17] + bb3*f[18] + bb4*f[19];

                __stcs(reinterpret_cast<float4*>(
                    actp + (size_t)r * (IN_DIM * OUT_DIM) + i * OUT_DIM), v);

                acc[r].x += v.x; acc[r].y += v.y; acc[r].z += v.z; acc[r].w += v.w;
            }
        }

        // publish next stage into the other buffer
        if (has) {
            float* dst = scoef + (buf ^ 1) * SC_BUF;
            #pragma unroll
            for (int k = 0; k < 10; k++) dst[t + THREADS * k] = p[k];
            if (t < SB_BUF) sbas[(buf ^ 1) * SB_BUF + t] = pb;
        }
        __syncthreads();
    }

    float* yp = y + (size_t)(b0 + rg2) * OUT_DIM + o4;
    #pragma unroll
    for (int r = 0; r < 2; r++)
        *reinterpret_cast<float4*>(yp + (size_t)r * OUT_DIM) = acc[r];
}

extern "C" void kernel_launch(void* const* d_in, const int* in_sizes, int n_in,
                              void* d_out, int out_size)
{
    const float* x     = (const float*)d_in[0];
    const float* grids = (const float*)d_in[1];
    const float* coef  = (const float*)d_in[2];

    const int B = in_sizes[0] / IN_DIM;   // 4096

    float* y    = (float*)d_out;
    float* acts = (float*)d_out + (size_t)B * OUT_DIM;

    kan_basis<<<B / ROWS, THREADS>>>(x, grids);

    cudaFuncSetAttribute(kan_main,
                         cudaFuncAttributeMaxDynamicSharedMemorySize, SMEM_BYTES);
    kan_main<<<B / ROWS, THREADS, SMEM_BYTES>>>(coef, y, acts);
}

// round 7
// speedup vs baseline: 1.4548x; 1.4548x over previous
#include <cuda_runtime.h>
#include <cstdint>

#define IN_DIM   256
#define OUT_DIM  256
#define N_KNOTS  9
#define NB       5
#define B_TILE   16
#define THREADS  288            // 8 consumer warps + 1 producer warp
#define CW       (OUT_DIM * NB) // 1280 coeff words per i-row

#define STAGES        3
#define ROWS_PER_STG  2
#define STAGE_WORDS   (ROWS_PER_STG * CW)     // 2560
#define NPAIR         (IN_DIM / ROWS_PER_STG) // 128

// shared-memory word layout
#define MBAR_WORDS 16                          // 3x(full,empty) 8B barriers
#define RING_OFF   MBAR_WORDS
#define RING_WORDS (STAGES * STAGE_WORDS)      // 7680
#define BASIS_OFF  (RING_OFF + RING_WORDS)
#define SB_WORDS   (IN_DIM * NB * B_TILE)      // 20480
#define SMEM_WORDS (BASIS_OFF + SB_WORDS)
#define SMEM_BYTES (SMEM_WORDS * 4)            // 112,704 B -> 2 CTAs/SM

// ---- mbarrier PTX helpers -------------------------------------------------
#define MBAR_INIT(addr, cnt) \
    asm volatile("mbarrier.init.shared.b64 [%0], %1;" :: "r"(addr), "r"(cnt) : "memory")
#define MBAR_ARRIVE(addr) \
    asm volatile("mbarrier.arrive.shared.b64 _, [%0];" :: "r"(addr) : "memory")
#define MBAR_WAIT(addr, parity) do {                                           \
    asm volatile(                                                              \
        "{\n\t.reg .pred P;\n\t"                                              \
        "WL_%=:\n\t"                                                          \
        "mbarrier.try_wait.parity.acquire.cta.shared::cta.b64 P, [%0], %1, 0x989680;\n\t" \
        "@P bra.uni WD_%=;\n\t"                                               \
        "bra.uni WL_%=;\n\t"                                                  \
        "WD_%=:\n\t}"                                                         \
        :: "r"(addr), "r"(parity) : "memory");                                \
} while (0)

__device__ __forceinline__ uint32_t smem_u32(const void* p) {
    uint32_t a;
    asm("{ .reg .u64 t; cvta.to.shared.u64 t, %1; cvt.u32.u64 %0, t; }"
        : "=r"(a) : "l"(p));
    return a;
}

__global__ __launch_bounds__(THREADS, 2)
void kan_kernel(const float* __restrict__ x,
                const float* __restrict__ grids,
                const float* __restrict__ coef,
                float* __restrict__ y,
                float* __restrict__ acts)
{
    extern __shared__ float smem[];
    float* ring   = smem + RING_OFF;    // [stage3][row2][1280] native [o][n]
    float* sbasis = smem + BASIS_OFF;   // [i][n][r16]
    const uint32_t mb = smem_u32(smem); // barriers at byte 0
    // full[s] = mb + s*16, empty[s] = mb + s*16 + 8

    const int t   = threadIdx.x;
    const int wid = t >> 5;
    const int b0  = blockIdx.x * B_TILE;

    if (t == 0) {
        #pragma unroll
        for (int s = 0; s < STAGES; s++) {
            MBAR_INIT(mb + s * 16,     32);  // full: 32 producer lanes
            MBAR_INIT(mb + s * 16 + 8,  8);  // empty: 8 elected consumer lanes
        }
    }

    // ------- Phase 1: basis for i = t (consumer threads only), 16 rows --------
    if (t < 256) {
        const int i = t;
        float tk[N_KNOTS];
        #pragma unroll
        for (int k = 0; k < N_KNOTS; k++) tk[k] = grids[i * N_KNOTS + k];

        float iL1[7], iR1[7], iL2[6], iR2[6], iL3[5], iR3[5];
        #pragma unroll
        for (int j = 0; j < 7; j++) { iL1[j] = 1.f / (tk[j+1] - tk[j]); iR1[j] = 1.f / (tk[j+2] - tk[j+1]); }
        #pragma unroll
        for (int j = 0; j < 6; j++) { iL2[j] = 1.f / (tk[j+2] - tk[j]); iR2[j] = 1.f / (tk[j+3] - tk[j+1]); }
        #pragma unroll
        for (int j = 0; j < 5; j++) { iL3[j] = 1.f / (tk[j+3] - tk[j]); iR3[j] = 1.f / (tk[j+4] - tk[j+1]); }

        const int rot = i & 15;
        #pragma unroll
        for (int rr = 0; rr < B_TILE; rr++) {
            const int r = (rr + rot) & 15;
            const float xv = x[(size_t)(b0 + r) * IN_DIM + i];
            float bas[8];
            #pragma unroll
            for (int j = 0; j < 8; j++)
                bas[j] = (xv >= tk[j] && xv < tk[j+1]) ? 1.0f : 0.0f;
            #pragma unroll
            for (int j = 0; j < 7; j++)
                bas[j] = (xv - tk[j]) * iL1[j] * bas[j] + (tk[j+2] - xv) * iR1[j] * bas[j+1];
            #pragma unroll
            for (int j = 0; j < 6; j++)
                bas[j] = (xv - tk[j]) * iL2[j] * bas[j] + (tk[j+3] - xv) * iR2[j] * bas[j+1];
            #pragma unroll
            for (int j = 0; j < 5; j++)
                bas[j] = (xv - tk[j]) * iL3[j] * bas[j] + (tk[j+4] - xv) * iR3[j] * bas[j+1];

            #pragma unroll
            for (int n = 0; n < NB; n++)
                sbasis[(i * NB + n) * B_TILE + r] = bas[n];
        }
    }
    __syncthreads();   // publishes basis + mbarrier init; the ONLY block barrier

    if (wid == 8) {
        // ---------------- Producer warp: stream coeff rows through the ring ---
        const int lane = t & 31;
        int s = 0, ph = 1;                      // fresh empties pass parity 1
        for (int p = 0; p < NPAIR; p++) {
            MBAR_WAIT(mb + s * 16 + 8, ph);     // wait stage empty
            const float4* src = reinterpret_cast<const float4*>(
                coef + (size_t)(2 * p) * CW);
            float4* dst = reinterpret_cast<float4*>(ring + s * STAGE_WORDS);
            float4 v[20];
            #pragma unroll
            for (int k = 0; k < 20; k++) v[k] = src[lane + 32 * k];
            #pragma unroll
            for (int k = 0; k < 20; k++) dst[lane + 32 * k] = v[k];
            MBAR_ARRIVE(mb + s * 16);           // all 32 lanes -> full
            if (++s == STAGES) { s = 0; ph ^= 1; }
        }
    } else {
        // ---------------- Consumer warps: o4 x 4 rows (proven R3/R5 tile) -----
        const int o4  = (t & 63) * 4;
        const int rg4 = (t >> 6) * 4;

        float4 acc[4];
        #pragma unroll
        for (int r = 0; r < 4; r++) acc[r] = make_float4(0.f, 0.f, 0.f, 0.f);

        float* actp = acts + (size_t)(b0 + rg4) * (IN_DIM * OUT_DIM) + o4;

        int s = 0, ph = 0;
        for (int p = 0; p < NPAIR; p++) {
            MBAR_WAIT(mb + s * 16, ph);         // wait stage full (acquire)

            #pragma unroll
            for (int sub = 0; sub < 2; sub++) {
                const int i = 2 * p + sub;

                // coeff: 20 consecutive words at o4*5 -> 5 conflict-free LDS.128
                float4 q[5];
                const float4* cb = reinterpret_cast<const float4*>(
                    &ring[s * STAGE_WORDS + sub * CW + o4 * NB]);
                #pragma unroll
                for (int j = 0; j < 5; j++) q[j] = cb[j];
                const float* f = reinterpret_cast<const float*>(q); // f[o*5+n]

                // basis: 5 broadcast LDS.128 (4 rows per n)
                float4 bs[NB];
                #pragma unroll
                for (int n = 0; n < NB; n++)
                    bs[n] = *reinterpret_cast<const float4*>(
                        &sbasis[(i * NB + n) * B_TILE + rg4]);

                #pragma unroll
                for (int r = 0; r < 4; r++) {
                    const float bb0 = reinterpret_cast<const float*>(&bs[0])[r];
                    const float bb1 = reinterpret_cast<const float*>(&bs[1])[r];
                    const float bb2 = reinterpret_cast<const float*>(&bs[2])[r];
                    const float bb3 = reinterpret_cast<const float*>(&bs[3])[r];
                    const float bb4 = reinterpret_cast<const float*>(&bs[4])[r];
                    float4 v;
                    v.x = bb0*f[ 0] + bb1*f[ 1] + bb2*f[ 2] + bb3*f[ 3] + bb4*f[ 4];
                    v.y = bb0*f[ 5] + bb1*f[ 6] + bb2*f[ 7] + bb3*f[ 8] + bb4*f[ 9];
                    v.z = bb0*f[10] + bb1*f[11] + bb2*f[12] + bb3*f[13] + bb4*f[14];
                    v.w = bb0*f[15] + bb1*f[16] + bb2*f[17] + bb3*f[18] + bb4*f[19];

                    __stcs(reinterpret_cast<float4*>(
                        actp + (size_t)r * (IN_DIM * OUT_DIM) + i * OUT_DIM), v);

                    acc[r].x += v.x; acc[r].y += v.y;
                    acc[r].z += v.z; acc[r].w += v.w;
                }
            }

            __syncwarp();
            if ((t & 31) == 0) MBAR_ARRIVE(mb + s * 16 + 8);   // release stage
            if (++s == STAGES) { s = 0; ph ^= 1; }
        }

        float* yp = y + (size_t)(b0 + rg4) * OUT_DIM + o4;
        #pragma unroll
        for (int r = 0; r < 4; r++)
            *reinterpret_cast<float4*>(yp + (size_t)r * OUT_DIM) = acc[r];
    }
}

extern "C" void kernel_launch(void* const* d_in, const int* in_sizes, int n_in,
                              void* d_out, int out_size)
{
    const float* x     = (const float*)d_in[0];
    const float* grids = (const float*)d_in[1];
    const float* coef  = (const float*)d_in[2];

    const int B = in_sizes[0] / IN_DIM;   // 4096

    float* y    = (float*)d_out;
    float* acts = (float*)d_out + (size_t)B * OUT_DIM;

    cudaFuncSetAttribute(kan_kernel,
                         cudaFuncAttributeMaxDynamicSharedMemorySize, SMEM_BYTES);
    kan_kernel<<<B / B_TILE, THREADS, SMEM_BYTES>>>(x, grids, coef, y, acts);
}